// round 1
// baseline (speedup 1.0000x reference)
#include <cuda_runtime.h>
#include <math.h>

#define B_  16
#define LC  2048
#define LQ  1024
#define D_  512

// ---------------- scratch (device globals; cudaMalloc is forbidden) -------
__device__ float g_S[(size_t)B_ * LC * LQ];   // 128 MiB: S[b,i,j] (j contiguous)
__device__ float g_cb[B_ * LC];               // context @ wc
__device__ float g_m [B_ * LQ];               // softmax max over i, per (b,j)
__device__ float g_w2[B_ * LQ];               // qmask[j] / Z[b,j]
__device__ float g_qmask[LQ];

// ---------------- kernel 1: cb = C@wc per row, qmask per query row --------
__global__ void k_bias(const float* __restrict__ ctx,
                       const float* __restrict__ q,
                       const float* __restrict__ w) {
    int gwarp = (blockIdx.x * blockDim.x + threadIdx.x) >> 5;
    int lane  = threadIdx.x & 31;
    const int nrows = B_ * LC + LQ;
    if (gwarp >= nrows) return;
    if (gwarp < B_ * LC) {
        const float4* row = (const float4*)(ctx + (size_t)gwarp * D_);
        const float4* wc4 = (const float4*)w;          // wc = w[0:512]
        float s = 0.f;
        #pragma unroll 4
        for (int k = lane; k < D_ / 4; k += 32) {
            float4 a = row[k], b = wc4[k];
            s += a.x * b.x + a.y * b.y + a.z * b.z + a.w * b.w;
        }
        #pragma unroll
        for (int o = 16; o; o >>= 1) s += __shfl_xor_sync(~0u, s, o);
        if (!lane) g_cb[gwarp] = s;
    } else {
        int j = gwarp - B_ * LC;
        const float4* row = (const float4*)(q + (size_t)j * D_);
        float s = 0.f;
        #pragma unroll 4
        for (int k = lane; k < D_ / 4; k += 32) {
            float4 a = row[k];
            s += a.x + a.y + a.z + a.w;
        }
        #pragma unroll
        for (int o = 16; o; o >>= 1) s += __shfl_xor_sync(~0u, s, o);
        if (!lane) g_qmask[j] = (s != 0.0f) ? 1.0f : 0.0f;
    }
}

// ---------------- kernel 2: S[b,i,j] = (C[b,i]*wm)·q[j] + cb[b,i] ---------
// (q·wq dropped: constant along the softmax axis, cancels exactly)
__global__ __launch_bounds__(256, 2)
void k_gemm_S(const float* __restrict__ ctx,
              const float* __restrict__ q,
              const float* __restrict__ w) {
    const int b  = blockIdx.z;
    const int i0 = blockIdx.y * 128;
    const int j0 = blockIdx.x * 128;
    const float* wm = w + 2 * D_;

    __shared__ float As[16][132];   // [k][i]
    __shared__ float Bs[16][132];   // [k][j]

    const int tid = threadIdx.x;
    const int tx  = tid & 15;       // 8 cols (j) each
    const int ty  = tid >> 4;       // 8 rows (i) each
    float acc[8][8] = {};

    const float* Abase = ctx + ((size_t)b * LC + i0) * D_;
    const float* Bbase = q + (size_t)j0 * D_;

    for (int k0 = 0; k0 < D_; k0 += 16) {
        #pragma unroll
        for (int p = 0; p < 2; p++) {
            int idx = tid + p * 256;            // 0..511
            int row = idx >> 2;                 // 0..127
            int kq  = (idx & 3) * 4;            // 0,4,8,12
            float4 a  = *(const float4*)(Abase + (size_t)row * D_ + k0 + kq);
            float4 wv = *(const float4*)(wm + k0 + kq);
            As[kq + 0][row] = a.x * wv.x;
            As[kq + 1][row] = a.y * wv.y;
            As[kq + 2][row] = a.z * wv.z;
            As[kq + 3][row] = a.w * wv.w;
            float4 bb = *(const float4*)(Bbase + (size_t)row * D_ + k0 + kq);
            Bs[kq + 0][row] = bb.x;
            Bs[kq + 1][row] = bb.y;
            Bs[kq + 2][row] = bb.z;
            Bs[kq + 3][row] = bb.w;
        }
        __syncthreads();
        #pragma unroll
        for (int kk = 0; kk < 16; kk++) {
            float ra[8], rb[8];
            #pragma unroll
            for (int r = 0; r < 8; r++) ra[r] = As[kk][ty * 8 + r];
            #pragma unroll
            for (int c = 0; c < 8; c++) rb[c] = Bs[kk][tx * 8 + c];
            #pragma unroll
            for (int r = 0; r < 8; r++)
                #pragma unroll
                for (int c = 0; c < 8; c++)
                    acc[r][c] = fmaf(ra[r], rb[c], acc[r][c]);
        }
        __syncthreads();
    }
    #pragma unroll
    for (int r = 0; r < 8; r++) {
        int i = i0 + ty * 8 + r;
        float cb = g_cb[b * LC + i];
        float* out = g_S + ((size_t)(b * LC + i)) * LQ + j0 + tx * 8;
        float4 o0 = {acc[r][0] + cb, acc[r][1] + cb, acc[r][2] + cb, acc[r][3] + cb};
        float4 o1 = {acc[r][4] + cb, acc[r][5] + cb, acc[r][6] + cb, acc[r][7] + cb};
        *(float4*)(out)     = o0;
        *(float4*)(out + 4) = o1;
    }
}

// ---------------- kernel 3: per-(b,j) online max + Z over i ---------------
__global__ void k_stats() {
    const int b  = blockIdx.y;
    const int j  = blockIdx.x * 128 + threadIdx.x;
    const int ty = threadIdx.y;                 // 0..3 i-strips
    const float* Sp = g_S + (size_t)b * LC * LQ + j;
    float m = -1e30f, Z = 0.f;
    for (int i = ty; i < LC; i += 4) {
        float s  = Sp[(size_t)i * LQ];
        float mn = fmaxf(m, s);
        Z = Z * __expf(m - mn) + __expf(s - mn);
        m = mn;
    }
    __shared__ float smm[4][128], smz[4][128];
    smm[ty][threadIdx.x] = m;
    smz[ty][threadIdx.x] = Z;
    __syncthreads();
    if (ty == 0) {
        float mm = m;
        #pragma unroll
        for (int t = 1; t < 4; t++) mm = fmaxf(mm, smm[t][threadIdx.x]);
        float ZZ = 0.f;
        #pragma unroll
        for (int t = 0; t < 4; t++) ZZ += smz[t][threadIdx.x] * __expf(smm[t][threadIdx.x] - mm);
        g_m [b * LQ + j] = mm;
        g_w2[b * LQ + j] = g_qmask[j] / ZZ;
    }
}

// ---------------- kernel 4: colsum over j + write G = [C, C*colsum] -------
__global__ void k_colsum_G(const float* __restrict__ ctx, float* __restrict__ G) {
    const int row = blockIdx.x;                 // b*LC + i
    const int b   = row >> 11;                  // LC = 2048
    const int tid = threadIdx.x;                // 128
    const float* Sp = g_S  + (size_t)row * LQ;
    const float* mp = g_m  + b * LQ;
    const float* wp = g_w2 + b * LQ;
    float a = 0.f;
    #pragma unroll
    for (int jj = tid; jj < LQ; jj += 128)
        a += __expf(Sp[jj] - mp[jj]) * wp[jj];
    #pragma unroll
    for (int o = 16; o; o >>= 1) a += __shfl_xor_sync(~0u, a, o);
    __shared__ float sred[4];
    if ((tid & 31) == 0) sred[tid >> 5] = a;
    __syncthreads();
    float cs = sred[0] + sred[1] + sred[2] + sred[3];
    const float4* c4 = (const float4*)(ctx + (size_t)row * D_);
    float4* g4 = (float4*)(G + (size_t)row * 2 * D_);
    float4 v = c4[tid];
    g4[tid] = v;
    float4 vw = {v.x * cs, v.y * cs, v.z * cs, v.w * cs};
    g4[128 + tid] = vw;
}

// ---------------- kernel 5: H[b,j,d] = sum_i A[b,j,i] * C[b,i,d] ----------
// A recomputed on the fly from S during the smem load.
__global__ __launch_bounds__(256, 2)
void k_gemm_H(const float* __restrict__ ctx, float* __restrict__ H) {
    const int b  = blockIdx.z;
    const int j0 = blockIdx.y * 128;
    const int d0 = blockIdx.x * 128;

    __shared__ float As[16][132];   // [i][j]  (A values)
    __shared__ float Bs[16][132];   // [i][d]
    __shared__ float sm_m[128], sm_w2[128];

    const int tid = threadIdx.x;
    const int tx  = tid & 15;       // d
    const int ty  = tid >> 4;       // j
    if (tid < 128) {
        sm_m [tid] = g_m [b * LQ + j0 + tid];
        sm_w2[tid] = g_w2[b * LQ + j0 + tid];
    }
    __syncthreads();

    float acc[8][8] = {};
    for (int k0 = 0; k0 < LC; k0 += 16) {
        #pragma unroll
        for (int p = 0; p < 2; p++) {
            int idx = tid + p * 256;            // 0..511
            int ii  = idx >> 5;                 // 0..15
            int jq  = (idx & 31) * 4;           // 0..124
            float4 s4 = *(const float4*)(g_S + ((size_t)(b * LC + k0 + ii)) * LQ + j0 + jq);
            As[ii][jq + 0] = __expf(s4.x - sm_m[jq + 0]) * sm_w2[jq + 0];
            As[ii][jq + 1] = __expf(s4.y - sm_m[jq + 1]) * sm_w2[jq + 1];
            As[ii][jq + 2] = __expf(s4.z - sm_m[jq + 2]) * sm_w2[jq + 2];
            As[ii][jq + 3] = __expf(s4.w - sm_m[jq + 3]) * sm_w2[jq + 3];
            float4 c4 = *(const float4*)(ctx + ((size_t)b * LC + k0 + ii) * D_ + d0 + jq);
            Bs[ii][jq + 0] = c4.x;
            Bs[ii][jq + 1] = c4.y;
            Bs[ii][jq + 2] = c4.z;
            Bs[ii][jq + 3] = c4.w;
        }
        __syncthreads();
        #pragma unroll
        for (int kk = 0; kk < 16; kk++) {
            float ra[8], rb[8];
            #pragma unroll
            for (int r = 0; r < 8; r++) ra[r] = As[kk][ty * 8 + r];
            #pragma unroll
            for (int c = 0; c < 8; c++) rb[c] = Bs[kk][tx * 8 + c];
            #pragma unroll
            for (int r = 0; r < 8; r++)
                #pragma unroll
                for (int c = 0; c < 8; c++)
                    acc[r][c] = fmaf(ra[r], rb[c], acc[r][c]);
        }
        __syncthreads();
    }
    #pragma unroll
    for (int r = 0; r < 8; r++) {
        int j = j0 + ty * 8 + r;
        float* out = H + ((size_t)b * LQ + j) * D_ + d0 + tx * 8;
        float4 o0 = {acc[r][0], acc[r][1], acc[r][2], acc[r][3]};
        float4 o1 = {acc[r][4], acc[r][5], acc[r][6], acc[r][7]};
        *(float4*)(out)     = o0;
        *(float4*)(out + 4) = o1;
    }
}

// ---------------- launch ---------------------------------------------------
extern "C" void kernel_launch(void* const* d_in, const int* in_sizes, int n_in,
                              void* d_out, int out_size) {
    // identify inputs by element count (robust to metadata ordering)
    const float *ctx = nullptr, *q = nullptr, *w = nullptr;
    for (int i = 0; i < n_in; i++) {
        if      (in_sizes[i] == B_ * LC * D_) ctx = (const float*)d_in[i];
        else if (in_sizes[i] == LQ * D_)      q   = (const float*)d_in[i];
        else if (in_sizes[i] == 3 * D_)       w   = (const float*)d_in[i];
    }
    float* G = (float*)d_out;                              // (B, LC, 2D)
    float* H = (float*)d_out + (size_t)B_ * LC * 2 * D_;   // (B, LQ, D)

    k_bias   <<<(B_ * LC + LQ + 7) / 8, 256>>>(ctx, q, w);
    k_gemm_S <<<dim3(LQ / 128, LC / 128, B_), 256>>>(ctx, q, w);
    k_stats  <<<dim3(LQ / 128, B_), dim3(128, 4)>>>();
    k_colsum_G<<<B_ * LC, 128>>>(ctx, G);
    k_gemm_H <<<dim3(D_ / 128, LQ / 128, B_), 256>>>(ctx, H);
}

// round 3
// speedup vs baseline: 2.6651x; 2.6651x over previous
#include <cuda_runtime.h>
#include <math.h>
#include <stdint.h>

#define B_  16
#define LC  2048
#define LQ  1024
#define D_  512
#define BK  32

// ---------------- scratch (device globals; cudaMalloc forbidden) ----------
__device__ float g_S [(size_t)B_ * LC * LQ];   // 128 MiB: S[b,i,j] (j contiguous)
__device__ float g_A [(size_t)B_ * LC * LQ];   // 128 MiB: A[b,i,j] (j contiguous)
__device__ float g_qm[(size_t)LQ * D_];        // 2 MiB : q * wm  [j,k]
__device__ float g_cb[B_ * LC];                // context @ wc
__device__ float g_m [B_ * LQ];                // softmax max over i per (b,j)
__device__ float g_w2[B_ * LQ];                // qmask[j] / Z[b,j]
__device__ float g_qmask[LQ];

// ---------------- helpers ---------------------------------------------------
__device__ __forceinline__ uint32_t smem_u32(const void* p) {
    uint32_t a;
    asm("{ .reg .u64 t; cvta.to.shared.u64 t, %1; cvt.u32.u64 %0, t; }" : "=r"(a) : "l"(p));
    return a;
}
__device__ __forceinline__ uint32_t f2tf(float x) {
    uint32_t y; asm("cvt.rna.tf32.f32 %0, %1;" : "=r"(y) : "f"(x)); return y;
}
#define CP16(sm, gp) \
    asm volatile("cp.async.cg.shared.global [%0], [%1], 16;" :: "r"(sm), "l"(gp))
#define CP_COMMIT() asm volatile("cp.async.commit_group;" ::: "memory")

#define MMA(c, a, b) \
    asm volatile("mma.sync.aligned.m16n8k8.row.col.f32.tf32.tf32.f32 " \
        "{%0,%1,%2,%3},{%4,%5,%6,%7},{%8,%9},{%0,%1,%2,%3};" \
        : "+f"((c)[0]), "+f"((c)[1]), "+f"((c)[2]), "+f"((c)[3]) \
        : "r"((a)[0]), "r"((a)[1]), "r"((a)[2]), "r"((a)[3]), \
          "r"((b)[0]), "r"((b)[1]))

// ---------------- kernel: cb = C@wc per row, qmask per query row ----------
__global__ void k_bias(const float* __restrict__ ctx,
                       const float* __restrict__ q,
                       const float* __restrict__ w) {
    int gwarp = (blockIdx.x * blockDim.x + threadIdx.x) >> 5;
    int lane  = threadIdx.x & 31;
    const int nrows = B_ * LC + LQ;
    if (gwarp >= nrows) return;
    if (gwarp < B_ * LC) {
        const float4* row = (const float4*)(ctx + (size_t)gwarp * D_);
        const float4* wc4 = (const float4*)w;
        float s = 0.f;
        #pragma unroll 4
        for (int k = lane; k < D_ / 4; k += 32) {
            float4 a = row[k], b = wc4[k];
            s += a.x * b.x + a.y * b.y + a.z * b.z + a.w * b.w;
        }
        #pragma unroll
        for (int o = 16; o; o >>= 1) s += __shfl_xor_sync(~0u, s, o);
        if (!lane) g_cb[gwarp] = s;
    } else {
        int j = gwarp - B_ * LC;
        const float4* row = (const float4*)(q + (size_t)j * D_);
        float s = 0.f;
        #pragma unroll 4
        for (int k = lane; k < D_ / 4; k += 32) {
            float4 a = row[k];
            s += a.x + a.y + a.z + a.w;
        }
        #pragma unroll
        for (int o = 16; o; o >>= 1) s += __shfl_xor_sync(~0u, s, o);
        if (!lane) g_qmask[j] = (s != 0.0f) ? 1.0f : 0.0f;
    }
}

// ---------------- kernel: qm[j,k] = q[j,k] * wm[k] -------------------------
__global__ void k_qm(const float* __restrict__ q, const float* __restrict__ w) {
    int j = blockIdx.x, t = threadIdx.x;   // 128 threads * float4 = 512
    const float4* q4 = (const float4*)(q + (size_t)j * D_);
    const float4* w4 = (const float4*)(w + 2 * D_);
    float4 a = q4[t], b = w4[t];
    float4 o = { a.x * b.x, a.y * b.y, a.z * b.z, a.w * b.w };
    ((float4*)(g_qm + (size_t)j * D_))[t] = o;
}

// ---------------- tf32 mma.sync GEMM, 128x128 block, 8 warps (64x32 each) --
// MODE 0: S[b,i,j] = ctx[b,i,:]·qm[j,:] + cb[b,i]        (K = 512)
//         A smem [m=128][k], stride 36   B smem [n=128][k], stride 36
// MODE 1: H[b,j,d] = A[b,:,j]·ctx[b,:,d]                 (K = 2048, k = i)
//         A smem [k=32][m=128], stride 132  B smem [k=32][n=128], stride 132
template<int MODE>
__global__ __launch_bounds__(256, 2) void k_mma(const float* __restrict__ gMain,
                                                float* __restrict__ gOut) {
    constexpr int KTOT  = MODE ? LC : D_;
    constexpr int NKC   = KTOT / BK;
    constexpr int STAGE = MODE ? (BK * 132) : (128 * 36);  // floats per operand

    extern __shared__ float sh[];
    float* sAb = sh;               // [2][STAGE]
    float* sBb = sh + 2 * STAGE;   // [2][STAGE]

    const int tid = threadIdx.x;
    const int b   = blockIdx.z;
    const int x0  = blockIdx.x * 128;   // MODE0: j0 ; MODE1: d0
    const int y0  = blockIdx.y * 128;   // MODE0: i0 ; MODE1: j0

    const float* Abase;
    const float* Bbase;
    if (MODE == 0) {
        Abase = gMain + ((size_t)b * LC + y0) * D_;          // ctx rows i
        Bbase = g_qm + (size_t)x0 * D_;                      // qm rows j
    } else {
        Abase = g_A + (size_t)b * LC * LQ + y0;              // A[b, k, j0+..]
        Bbase = gMain + (size_t)b * LC * D_ + x0;            // ctx[b, k, d0+..]
    }

    auto load = [&](int c, int stage) {
        float* dA = sAb + stage * STAGE;
        float* dB = sBb + stage * STAGE;
        const int k0 = c * BK;
        if (MODE == 0) {
            #pragma unroll
            for (int p = 0; p < 4; p++) {
                int idx = tid + p * 256;          // 1024 cp16 per operand
                int row = idx >> 3, seg = idx & 7;
                CP16(smem_u32(dA + row * 36 + seg * 4),
                     Abase + (size_t)row * D_ + k0 + seg * 4);
                CP16(smem_u32(dB + row * 36 + seg * 4),
                     Bbase + (size_t)row * D_ + k0 + seg * 4);
            }
        } else {
            #pragma unroll
            for (int p = 0; p < 4; p++) {
                int idx = tid + p * 256;          // 32 rows x 32 cp16
                int row = idx >> 5, seg = idx & 31;
                CP16(smem_u32(dA + row * 132 + seg * 4),
                     Abase + (size_t)(k0 + row) * LQ + seg * 4);
                CP16(smem_u32(dB + row * 132 + seg * 4),
                     Bbase + (size_t)(k0 + row) * D_ + seg * 4);
            }
        }
    };

    const int lane  = tid & 31, wrp = tid >> 5;
    const int mbase = (wrp & 1) * 64, nbase = (wrp >> 1) * 32;
    const int lr    = lane >> 2, lk = lane & 3;

    float acc[4][4][4];
    #pragma unroll
    for (int mt = 0; mt < 4; mt++)
        #pragma unroll
        for (int nt = 0; nt < 4; nt++)
            #pragma unroll
            for (int e = 0; e < 4; e++) acc[mt][nt][e] = 0.f;

    auto compute = [&](int stage) {
        const float* A  = sAb + stage * STAGE;
        const float* Bp = sBb + stage * STAGE;
        #pragma unroll
        for (int kk = 0; kk < BK; kk += 8) {
            uint32_t af[4][4], bf[4][2];
            #pragma unroll
            for (int mt = 0; mt < 4; mt++) {
                int r = mbase + mt * 16 + lr;
                if (MODE == 0) {
                    af[mt][0] = f2tf(A[r * 36 + kk + lk]);
                    af[mt][1] = f2tf(A[(r + 8) * 36 + kk + lk]);
                    af[mt][2] = f2tf(A[r * 36 + kk + lk + 4]);
                    af[mt][3] = f2tf(A[(r + 8) * 36 + kk + lk + 4]);
                } else {
                    af[mt][0] = f2tf(A[(kk + lk) * 132 + r]);
                    af[mt][1] = f2tf(A[(kk + lk) * 132 + r + 8]);
                    af[mt][2] = f2tf(A[(kk + lk + 4) * 132 + r]);
                    af[mt][3] = f2tf(A[(kk + lk + 4) * 132 + r + 8]);
                }
            }
            #pragma unroll
            for (int nt = 0; nt < 4; nt++) {
                int cix = nbase + nt * 8 + lr;
                if (MODE == 0) {
                    bf[nt][0] = f2tf(Bp[cix * 36 + kk + lk]);
                    bf[nt][1] = f2tf(Bp[cix * 36 + kk + lk + 4]);
                } else {
                    bf[nt][0] = f2tf(Bp[(kk + lk) * 132 + cix]);
                    bf[nt][1] = f2tf(Bp[(kk + lk + 4) * 132 + cix]);
                }
            }
            #pragma unroll
            for (int mt = 0; mt < 4; mt++)
                #pragma unroll
                for (int nt = 0; nt < 4; nt++)
                    MMA(acc[mt][nt], af[mt], bf[nt]);
        }
    };

    load(0, 0); CP_COMMIT();
    load(1, 1); CP_COMMIT();
    for (int c = 0; c < NKC; c++) {
        asm volatile("cp.async.wait_group 1;" ::: "memory");
        __syncthreads();
        compute(c & 1);
        __syncthreads();
        if (c + 2 < NKC) load(c + 2, c & 1);
        CP_COMMIT();
    }

    if (MODE == 0) {
        #pragma unroll
        for (int mt = 0; mt < 4; mt++) {
            int i = y0 + mbase + mt * 16 + lr;
            float c0 = g_cb[b * LC + i];
            float c8 = g_cb[b * LC + i + 8];
            #pragma unroll
            for (int nt = 0; nt < 4; nt++) {
                int j = x0 + nbase + nt * 8 + 2 * lk;
                float2 v0 = make_float2(acc[mt][nt][0] + c0, acc[mt][nt][1] + c0);
                float2 v1 = make_float2(acc[mt][nt][2] + c8, acc[mt][nt][3] + c8);
                *(float2*)(g_S + ((size_t)(b * LC + i)) * LQ + j)     = v0;
                *(float2*)(g_S + ((size_t)(b * LC + i + 8)) * LQ + j) = v1;
            }
        }
    } else {
        #pragma unroll
        for (int mt = 0; mt < 4; mt++) {
            int j = y0 + mbase + mt * 16 + lr;
            #pragma unroll
            for (int nt = 0; nt < 4; nt++) {
                int d = x0 + nbase + nt * 8 + 2 * lk;
                float2 v0 = make_float2(acc[mt][nt][0], acc[mt][nt][1]);
                float2 v1 = make_float2(acc[mt][nt][2], acc[mt][nt][3]);
                *(float2*)(gOut + ((size_t)(b * LQ + j)) * D_ + d)     = v0;
                *(float2*)(gOut + ((size_t)(b * LQ + j + 8)) * D_ + d) = v1;
            }
        }
    }
}

// ---------------- kernel: per-(b,j) max + Z over i --------------------------
__global__ void k_stats() {
    const int b  = blockIdx.y;
    const int j  = blockIdx.x * 128 + threadIdx.x;
    const int ty = threadIdx.y;                 // 0..3 i-strips
    const float* Sp = g_S + (size_t)b * LC * LQ + j;
    float m = -1e30f, Z = 0.f;
    for (int i = ty; i < LC; i += 4) {
        float s = Sp[(size_t)i * LQ];
        if (s > m) { Z *= __expf(m - s); m = s; }
        Z += __expf(s - m);
    }
    __shared__ float smm[4][128], smz[4][128];
    smm[ty][threadIdx.x] = m;
    smz[ty][threadIdx.x] = Z;
    __syncthreads();
    if (ty == 0) {
        float mm = m;
        #pragma unroll
        for (int t = 1; t < 4; t++) mm = fmaxf(mm, smm[t][threadIdx.x]);
        float ZZ = 0.f;
        #pragma unroll
        for (int t = 0; t < 4; t++) ZZ += smz[t][threadIdx.x] * __expf(smm[t][threadIdx.x] - mm);
        g_m [b * LQ + j] = mm;
        g_w2[b * LQ + j] = g_qmask[j] / ZZ;
    }
}

// ---------------- kernel: A[b,i,j] + colsum + G (fused) ---------------------
__global__ __launch_bounds__(256) void k_colsum_AG(const float* __restrict__ ctx,
                                                   float* __restrict__ G) {
    const int b = blockIdx.y;
    __shared__ float sm[LQ], sw[LQ];
    for (int t = threadIdx.x; t < LQ; t += 256) {
        sm[t] = g_m [b * LQ + t];
        sw[t] = g_w2[b * LQ + t];
    }
    __syncthreads();
    const int wrp = threadIdx.x >> 5, lane = threadIdx.x & 31;
    const size_t row = (size_t)b * LC + blockIdx.x * 8 + wrp;
    const float4* S4 = (const float4*)(g_S + row * LQ);
    float4* A4 = (float4*)(g_A + row * LQ);
    float cs = 0.f;
    #pragma unroll 2
    for (int t = lane; t < LQ / 4; t += 32) {
        float4 s = S4[t];
        int j = t * 4;
        float a0 = __expf(s.x - sm[j + 0]) * sw[j + 0];
        float a1 = __expf(s.y - sm[j + 1]) * sw[j + 1];
        float a2 = __expf(s.z - sm[j + 2]) * sw[j + 2];
        float a3 = __expf(s.w - sm[j + 3]) * sw[j + 3];
        cs += (a0 + a1) + (a2 + a3);
        A4[t] = make_float4(a0, a1, a2, a3);
    }
    #pragma unroll
    for (int o = 16; o; o >>= 1) cs += __shfl_xor_sync(~0u, cs, o);
    const float4* c4 = (const float4*)(ctx + row * D_);
    float4* g4 = (float4*)(G + row * 2 * D_);
    #pragma unroll
    for (int t = lane; t < D_ / 4; t += 32) {
        float4 v = c4[t];
        g4[t] = v;
        g4[128 + t] = make_float4(v.x * cs, v.y * cs, v.z * cs, v.w * cs);
    }
}

// ---------------- launch -----------------------------------------------------
extern "C" void kernel_launch(void* const* d_in, const int* in_sizes, int n_in,
                              void* d_out, int out_size) {
    const float *ctx = nullptr, *q = nullptr, *w = nullptr;
    for (int i = 0; i < n_in; i++) {
        if      (in_sizes[i] == B_ * LC * D_) ctx = (const float*)d_in[i];
        else if (in_sizes[i] == LQ * D_)      q   = (const float*)d_in[i];
        else if (in_sizes[i] == 3 * D_)       w   = (const float*)d_in[i];
    }
    float* G = (float*)d_out;                              // (B, LC, 2D)
    float* H = (float*)d_out + (size_t)B_ * LC * 2 * D_;   // (B, LQ, D)

    const int smem0 = 2 * 2 * 128 * 36 * 4;   // 73728
    const int smem1 = 2 * 2 * BK * 132 * 4;   // 67584
    cudaFuncSetAttribute(k_mma<0>, cudaFuncAttributeMaxDynamicSharedMemorySize, smem0);
    cudaFuncSetAttribute(k_mma<1>, cudaFuncAttributeMaxDynamicSharedMemorySize, smem1);

    k_bias     <<<(B_ * LC + LQ + 7) / 8, 256>>>(ctx, q, w);
    k_qm       <<<LQ, 128>>>(q, w);
    k_mma<0>   <<<dim3(LQ / 128, LC / 128, B_), 256, smem0>>>(ctx, nullptr);
    k_stats    <<<dim3(LQ / 128, B_), dim3(128, 4)>>>();
    k_colsum_AG<<<dim3(LC / 8, B_), 256>>>(ctx, G);
    k_mma<1>   <<<dim3(D_ / 128, LQ / 128, B_), 256, smem1>>>(ctx, H);
}